// round 13
// baseline (speedup 1.0000x reference)
#include <cuda_runtime.h>
#include <cuda_fp16.h>
#include <cstdint>
#include <cstddef>

#define D         256
#define K         1024
#define TP        256            // positions per CTA (M)
#define NTHREADS  512
#define NBLOCKS   128
#define OUT_ELEMS 8388608
#define XROW      264            // X smem row (halfs): 528B
#define WROWH     72             // W smem row (halfs): 144B
#define EPSILON   1.0f
#define QCAP      4096

// ---- smem byte layout ----
#define OFF_XH    0              // 256*264*2 = 135168
#define OFF_WH0   135168         // 64*72*2 = 9216
#define OFF_WH1   144384         // 9216
#define OFF_WSQ   153600         // 4096
#define OFF_QPK   157696         // 16384
#define OFF_QVAL  174080         // 16384
#define OFF_REDV  190464         // 256*2 f32 = 2048
#define OFF_MAXV  192512         // 256 f32
#define OFF_SIDX  193536         // 256 i32
#define OFF_SRED  194560         // 512 f32
#define OFF_CTL   196608
#define SMEM_A    196624
#define OFF_TBUF  OFF_WH0        // 16x264 f32 transpose buffer (X-fill only, spans W bufs)

__device__ float          g_wsq[K];
__device__ unsigned short g_whi[K * D];
__device__ float          g_partial[NBLOCKS];
__device__ int            g_count;

__device__ __forceinline__ uint32_t smem_u32(const void* p) {
    uint32_t a;
    asm("{ .reg .u64 t; cvta.to.shared.u64 t, %1; cvt.u32.u64 %0, t; }" : "=r"(a) : "l"(p));
    return a;
}
__device__ __forceinline__ void ldsm4(uint32_t* r, uint32_t addr) {
    asm volatile("ldmatrix.sync.aligned.m8n8.x4.shared.b16 {%0,%1,%2,%3}, [%4];"
                 : "=r"(r[0]), "=r"(r[1]), "=r"(r[2]), "=r"(r[3]) : "r"(addr));
}
__device__ __forceinline__ void mma16816(float* c, const uint32_t* a, const uint32_t* b) {
    asm volatile(
        "mma.sync.aligned.m16n8k16.row.col.f32.f16.f16.f32 "
        "{%0,%1,%2,%3}, {%4,%5,%6,%7}, {%8,%9}, {%0,%1,%2,%3};"
        : "+f"(c[0]), "+f"(c[1]), "+f"(c[2]), "+f"(c[3])
        : "r"(a[0]), "r"(a[1]), "r"(a[2]), "r"(a[3]), "r"(b[0]), "r"(b[1]));
}

// ---- prep: 0.5*||w||^2 + fp16 hi of W (warp per row) ----
__global__ void vq_prep(const float* __restrict__ wgt)
{
    int wid  = threadIdx.x >> 5;
    int lane = threadIdx.x & 31;
    int row  = blockIdx.x * 8 + wid;
    const float4* r = (const float4*)(wgt + (size_t)row * D);
    float4 a = r[lane];
    float4 b = r[lane + 32];
    float s = a.x * a.x;
    s = fmaf(a.y, a.y, s); s = fmaf(a.z, a.z, s); s = fmaf(a.w, a.w, s);
    s = fmaf(b.x, b.x, s); s = fmaf(b.y, b.y, s);
    s = fmaf(b.z, b.z, s); s = fmaf(b.w, b.w, s);
    #pragma unroll
    for (int o = 16; o > 0; o >>= 1) s += __shfl_xor_sync(0xffffffffu, s, o);
    if (lane == 0) g_wsq[row] = 0.5f * s;

    float v[2][4] = {{a.x, a.y, a.z, a.w}, {b.x, b.y, b.z, b.w}};
    #pragma unroll
    for (int h = 0; h < 2; ++h) {
        unsigned short ph[4];
        #pragma unroll
        for (int i = 0; i < 4; ++i)
            ph[i] = __half_as_ushort(__float2half_rn(v[h][i]));
        *(uint2*)(g_whi + (size_t)row * D + h * 128 + lane * 4) = *(uint2*)ph;
    }
}

// ---- fused main: TP=256, hi-only GEMM + in-fold candidates + exact rescue ----
__global__ void __launch_bounds__(NTHREADS, 1)
vq_main(const float* __restrict__ inp, const float* __restrict__ wgt,
        float* __restrict__ out, int loss_index)
{
    extern __shared__ char smem[];
    const uint32_t sb = smem_u32(smem);
    float* wsq_s = (float*)(smem + OFF_WSQ);
    float* tbuf  = (float*)(smem + OFF_TBUF);
    unsigned short* Xh = (unsigned short*)(smem + OFF_XH);
    int*   qpk  = (int*)(smem + OFF_QPK);
    float* qval = (float*)(smem + OFF_QVAL);
    float* redv = (float*)(smem + OFF_REDV);
    float* maxv = (float*)(smem + OFF_MAXV);
    int*   sidx = (int*)(smem + OFF_SIDX);
    float* sred = (float*)(smem + OFF_SRED);
    int*   ctl  = (int*)(smem + OFF_CTL);     // [0]=qn, [1]=sflg

    const int tid  = threadIdx.x;
    const int lane = tid & 31;
    const int warp = tid >> 5;
    const int g    = lane >> 2;
    const int t    = lane & 3;
    const int wN   = warp & 1;       // 2 N-groups of 32 codes
    const int wM   = warp >> 1;      // 8 M-groups of 32 positions
    const int mi   = lane >> 3;
    const int mr   = lane & 7;

    const int n0  = blockIdx.x * TP;
    const int b   = n0 >> 10;
    const int hw0 = n0 & 1023;
    const float* xin = inp + (((size_t)b * D) << 10) + hw0;

    wsq_s[tid]       = g_wsq[tid];
    wsq_s[tid + 512] = g_wsq[tid + 512];
    if (tid == 0) ctl[0] = 0;
    if (tid < TP) maxv[tid] = -1e30f;

    int parr[4];
    #pragma unroll
    for (int s = 0; s < 4; ++s)
        parr[s] = wM * 32 + (s >> 1) * 16 + (s & 1) * 8 + g;

    uint32_t aXh[2], rB[2];
    #pragma unroll
    for (int mt = 0; mt < 2; ++mt)
        aXh[mt] = sb + OFF_XH +
            (uint32_t)((wM * 32 + mt * 16 + (mi & 1) * 8 + mr) * XROW + (mi >> 1) * 8) * 2;
    #pragma unroll
    for (int q = 0; q < 2; ++q)
        rB[q] = (uint32_t)((wN * 32 + (q * 2 + (mi >> 1)) * 8 + mr) * WROWH + (mi & 1) * 8) * 2;

    // prefetch W piece 0 (codes 0..63, dims 0..63): 1 uint4/thread
    uint4 fh;
    {
        int code = tid >> 3, seg = tid & 7;
        fh = *(const uint4*)(g_whi + (size_t)code * D + seg * 8);
    }

    // ---- X transpose + fp16 hi: 16 slices of 16 dims x 256 pos ----
    for (int dc = 0; dc < 16; ++dc) {
        {
            int d  = tid >> 5;             // 0..15
            int p0 = (tid & 31) << 3;      // 8 positions
            const float* src = xin + (((size_t)(dc * 16 + d)) << 10) + p0;
            float4 v0 = *(const float4*)(src);
            float4 v1 = *(const float4*)(src + 4);
            float* dst = tbuf + d * 264 + p0;
            dst[0]=v0.x; dst[1]=v0.y; dst[2]=v0.z; dst[3]=v0.w;
            dst[4]=v1.x; dst[5]=v1.y; dst[6]=v1.z; dst[7]=v1.w;
        }
        __syncthreads();
        {
            int p  = tid & 255;
            int dq = tid >> 8;             // 0/1 -> dims dq*8..dq*8+7
            uint32_t ph[4];
            #pragma unroll
            for (int i = 0; i < 4; ++i) {
                __half h0 = __float2half_rn(tbuf[(dq * 8 + 2 * i    ) * 264 + p]);
                __half h1 = __float2half_rn(tbuf[(dq * 8 + 2 * i + 1) * 264 + p]);
                ph[i] = (uint32_t)__half_as_ushort(h0) | ((uint32_t)__half_as_ushort(h1) << 16);
            }
            *(uint4*)(Xh + p * XROW + dc * 16 + dq * 8) = make_uint4(ph[0], ph[1], ph[2], ph[3]);
        }
        __syncthreads();
    }

    float acc[2][4][4];
    #pragma unroll
    for (int mt = 0; mt < 2; ++mt)
        #pragma unroll
        for (int nt = 0; nt < 4; ++nt)
            #pragma unroll
            for (int j = 0; j < 4; ++j) acc[mt][nt][j] = 0.f;

    // ---- main loop: 64 pieces = 16 nc (64 codes) x 4 kc (64 dims) ----
    for (int piece = 0; piece < 64; ++piece) {
        const int nc   = piece >> 2;
        const int kc   = piece & 3;
        const int bsel = piece & 1;
        unsigned short* WhB = (unsigned short*)(smem + (bsel ? OFF_WH1 : OFF_WH0));

        {
            int code = tid >> 3, seg = tid & 7;
            *(uint4*)(WhB + code * WROWH + seg * 8) = fh;
        }
        if (piece + 1 < 64) {
            int nn = (piece + 1) >> 2, nk = (piece + 1) & 3;
            int code = tid >> 3, seg = tid & 7;
            fh = *(const uint4*)(g_whi + (size_t)(nn * 64 + code) * D + nk * 64 + seg * 8);
        }
        __syncthreads();   // buffer[bsel] ready; compute on it from piece-2 done

        const uint32_t wbh = sb + (bsel ? OFF_WH1 : OFF_WH0);
        const uint32_t ao0 = (uint32_t)kc * 128;
        #pragma unroll
        for (int ks = 0; ks < 4; ++ks) {
            uint32_t ah0[4], ah1[4], bh[8];
            uint32_t ao = ao0 + ks * 32;
            ldsm4(ah0, aXh[0] + ao);
            ldsm4(ah1, aXh[1] + ao);
            ldsm4(bh + 0, wbh + rB[0] + ks * 32);
            ldsm4(bh + 4, wbh + rB[1] + ks * 32);
            #pragma unroll
            for (int nt = 0; nt < 4; ++nt) {
                mma16816(acc[0][nt], ah0, &bh[nt * 2]);
                mma16816(acc[1][nt], ah1, &bh[nt * 2]);
            }
        }

        if (kc == 3) {
            // finalize chunk scores: s = acc - 0.5||w||^2; chunk max
            float cmax[4] = {-1e30f, -1e30f, -1e30f, -1e30f};
            #pragma unroll
            for (int mt = 0; mt < 2; ++mt)
                #pragma unroll
                for (int nt = 0; nt < 4; ++nt)
                    #pragma unroll
                    for (int j = 0; j < 4; ++j) {
                        int nl = wN * 32 + nt * 8 + 2 * t + (j & 1);
                        float s = acc[mt][nt][j] - wsq_s[nc * 64 + nl];
                        acc[mt][nt][j] = s;
                        int slot = mt * 2 + (j >> 1);
                        cmax[slot] = fmaxf(cmax[slot], s);
                    }
            #pragma unroll
            for (int o = 1; o <= 2; o <<= 1)
                #pragma unroll
                for (int s = 0; s < 4; ++s)
                    cmax[s] = fmaxf(cmax[s], __shfl_xor_sync(0xffffffffu, cmax[s], o));
            if (t == 0) {
                #pragma unroll
                for (int s = 0; s < 4; ++s)
                    redv[parr[s] * 2 + wN] = cmax[s];
            }
            __syncthreads();
            if (tid < TP)
                maxv[tid] = fmaxf(maxv[tid], fmaxf(redv[tid * 2], redv[tid * 2 + 1]));
            __syncthreads();
            // push candidates >= running max - eps (superset of final set)
            #pragma unroll
            for (int mt = 0; mt < 2; ++mt)
                #pragma unroll
                for (int nt = 0; nt < 4; ++nt)
                    #pragma unroll
                    for (int j = 0; j < 4; ++j) {
                        int slot = mt * 2 + (j >> 1);
                        float s = acc[mt][nt][j];
                        if (s >= maxv[parr[slot]] - EPSILON) {
                            int k = nc * 64 + wN * 32 + nt * 8 + 2 * t + (j & 1);
                            int idx = atomicAdd(&ctl[0], 1);
                            if (idx < QCAP) qpk[idx] = (parr[slot] << 16) | k;
                        }
                        acc[mt][nt][j] = 0.f;
                    }
        }
    }
    __syncthreads();
    const int nq = (ctl[0] < QCAP) ? ctl[0] : QCAP;

    // ---- warp-cooperative exact rescue: fp32 x from global (L2-hot), w fp32 ----
    for (int ci = warp; ci < nq; ci += 16) {
        int pk = qpk[ci];
        int cp = pk >> 16, ck = pk & 1023;
        const float* wr = wgt + (size_t)ck * D;
        const float* xr = xin + cp;
        float a = 0.f;
        #pragma unroll
        for (int m = 0; m < 8; ++m) {
            int d = lane + 32 * m;
            a = fmaf(__ldg(xr + (((size_t)d) << 10)), __ldg(wr + d), a);
        }
        #pragma unroll
        for (int o = 16; o > 0; o >>= 1) a += __shfl_xor_sync(0xffffffffu, a, o);
        if (lane == 0) qval[ci] = a - wsq_s[ck];
    }
    __syncthreads();

    // ---- per-position exact argmax over candidates (order-independent) ----
    if (tid < TP) {
        float bv = -1e30f;
        int   bk = 0;
        for (int i = 0; i < nq; ++i) {
            int pk = qpk[i];
            if ((pk >> 16) == tid) {
                float v = qval[i];
                int   k = pk & 1023;
                if (v > bv || (v == bv && k < bk)) { bv = v; bk = k; }
            }
        }
        sidx[tid] = bk;
    }
    __syncthreads();

    // ---- output: gather + NCHW write + loss partial ----
    {
        int p  = tid & 255;
        int ds = tid >> 8;
        int myidx = sidx[p];
        const float4* wrow = (const float4*)(wgt + (size_t)myidx * D);
        float* op = out + (((size_t)b * D) << 10) + hw0 + p;
        const float* xp = xin + p;
        float lsum = 0.f;
        #pragma unroll 4
        for (int i = 0; i < 32; ++i) {
            int gq = ds + (i << 1);
            float4 qv = __ldg(wrow + gq);
            float x0 = xp[((size_t)(4 * gq + 0)) << 10];
            float x1 = xp[((size_t)(4 * gq + 1)) << 10];
            float x2 = xp[((size_t)(4 * gq + 2)) << 10];
            float x3 = xp[((size_t)(4 * gq + 3)) << 10];
            float d0 = qv.x - x0, d1 = qv.y - x1, d2 = qv.z - x2, d3 = qv.w - x3;
            lsum = fmaf(d0, d0, lsum); lsum = fmaf(d1, d1, lsum);
            lsum = fmaf(d2, d2, lsum); lsum = fmaf(d3, d3, lsum);
            op[((size_t)(4 * gq + 0)) << 10] = qv.x;
            op[((size_t)(4 * gq + 1)) << 10] = qv.y;
            op[((size_t)(4 * gq + 2)) << 10] = qv.z;
            op[((size_t)(4 * gq + 3)) << 10] = qv.w;
        }
        sred[tid] = lsum;
    }
    __syncthreads();
    #pragma unroll
    for (int s = NTHREADS / 2; s > 0; s >>= 1) {
        if (tid < s) sred[tid] += sred[tid + s];
        __syncthreads();
    }
    if (tid == 0) g_partial[blockIdx.x] = sred[0];

    // ---- last-block loss finalize (deterministic; counter self-resets) ----
    if (tid == 0) {
        __threadfence();
        int c = atomicAdd(&g_count, 1);
        ctl[1] = (c == NBLOCKS - 1) ? 1 : 0;
    }
    __syncthreads();
    if (ctl[1]) {
        __threadfence();
        sred[tid] = (tid < NBLOCKS) ? g_partial[tid] : 0.f;
        __syncthreads();
        #pragma unroll
        for (int s = NTHREADS / 2; s > 0; s >>= 1) {
            if (tid < s) sred[tid] += sred[tid + s];
            __syncthreads();
        }
        if (tid == 0) {
            out[loss_index] = 1.25f * sred[0] / (float)OUT_ELEMS;
            g_count = 0;
        }
    }
}

extern "C" void kernel_launch(void* const* d_in, const int* in_sizes, int n_in,
                              void* d_out, int out_size)
{
    (void)in_sizes; (void)n_in;
    const float* inp = (const float*)d_in[0];   // [32,256,32,32] fp32 NCHW
    const float* wgt = (const float*)d_in[1];   // [1024,256] fp32
    float* out = (float*)d_out;

    (void)cudaFuncSetAttribute(vq_main, cudaFuncAttributeMaxDynamicSharedMemorySize,
                               SMEM_A);

    vq_prep<<<K / 8, 256>>>(wgt);
    vq_main<<<NBLOCKS, NTHREADS, SMEM_A>>>(inp, wgt, out, out_size - 1);
}

// round 15
// speedup vs baseline: 1.1786x; 1.1786x over previous
#include <cuda_runtime.h>
#include <cuda_fp16.h>
#include <cstdint>
#include <cstddef>

#define D         256
#define K         1024
#define TP        64             // positions per CTA
#define NTHREADS  256
#define NBLOCKS   512
#define OUT_ELEMS 8388608
#define XROW      264            // X smem row (halfs): 528B
#define WROWH     72             // W smem row (halfs): 144B
#define EPSILON   1.0f
#define QCAP      2048

// ---- smem byte layout (total ~94KB -> 2 CTAs/SM) ----
#define OFF_XH    0              // 64*264*2 = 33792
#define OFF_WH0   33792          // 128*72*2 = 18432
#define OFF_WH1   52224          // 18432
#define OFF_WSQ   70656          // 4096
#define OFF_QPK   74752          // 8192 (2048 i32)
#define OFF_QVAL  82944          // 8192
#define OFF_REDV  91136          // 64*4 f32 = 1024
#define OFF_MAXV  92160          // 64 f32
#define OFF_SIDX  92416          // 64 i32
#define OFF_SRED  92672          // 256 f32
#define OFF_CTL   93696          // qn, sflg
#define SMEM_A    93712
#define OFF_TBUF  OFF_WH0        // 32x68 f32 transpose buffer (X-fill only, 8704B)

__device__ float          g_wsq[K];
__device__ unsigned short g_whi[K * D];
__device__ float          g_partial[NBLOCKS];
__device__ int            g_count;

__device__ __forceinline__ uint32_t smem_u32(const void* p) {
    uint32_t a;
    asm("{ .reg .u64 t; cvta.to.shared.u64 t, %1; cvt.u32.u64 %0, t; }" : "=r"(a) : "l"(p));
    return a;
}
__device__ __forceinline__ void ldsm4(uint32_t* r, uint32_t addr) {
    asm volatile("ldmatrix.sync.aligned.m8n8.x4.shared.b16 {%0,%1,%2,%3}, [%4];"
                 : "=r"(r[0]), "=r"(r[1]), "=r"(r[2]), "=r"(r[3]) : "r"(addr));
}
__device__ __forceinline__ void mma16816(float* c, const uint32_t* a, const uint32_t* b) {
    asm volatile(
        "mma.sync.aligned.m16n8k16.row.col.f32.f16.f16.f32 "
        "{%0,%1,%2,%3}, {%4,%5,%6,%7}, {%8,%9}, {%0,%1,%2,%3};"
        : "+f"(c[0]), "+f"(c[1]), "+f"(c[2]), "+f"(c[3])
        : "r"(a[0]), "r"(a[1]), "r"(a[2]), "r"(a[3]), "r"(b[0]), "r"(b[1]));
}

// ---- prep: 0.5*||w||^2 + fp16 hi of W (warp per row) ----
__global__ void vq_prep(const float* __restrict__ wgt)
{
    int wid  = threadIdx.x >> 5;
    int lane = threadIdx.x & 31;
    int row  = blockIdx.x * 8 + wid;
    const float4* r = (const float4*)(wgt + (size_t)row * D);
    float4 a = r[lane];
    float4 b = r[lane + 32];
    float s = a.x * a.x;
    s = fmaf(a.y, a.y, s); s = fmaf(a.z, a.z, s); s = fmaf(a.w, a.w, s);
    s = fmaf(b.x, b.x, s); s = fmaf(b.y, b.y, s);
    s = fmaf(b.z, b.z, s); s = fmaf(b.w, b.w, s);
    #pragma unroll
    for (int o = 16; o > 0; o >>= 1) s += __shfl_xor_sync(0xffffffffu, s, o);
    if (lane == 0) g_wsq[row] = 0.5f * s;

    float v[2][4] = {{a.x, a.y, a.z, a.w}, {b.x, b.y, b.z, b.w}};
    #pragma unroll
    for (int h = 0; h < 2; ++h) {
        unsigned short ph[4];
        #pragma unroll
        for (int i = 0; i < 4; ++i)
            ph[i] = __half_as_ushort(__float2half_rn(v[h][i]));
        *(uint2*)(g_whi + (size_t)row * D + h * 128 + lane * 4) = *(uint2*)ph;
    }
}

// ---- fused main: TP=64, 2 CTAs/SM; hi-only GEMM + in-fold candidates + rescue ----
__global__ void __launch_bounds__(NTHREADS, 2)
vq_main(const float* __restrict__ inp, const float* __restrict__ wgt,
        float* __restrict__ out, int loss_index)
{
    extern __shared__ char smem[];
    const uint32_t sb = smem_u32(smem);
    float* wsq_s = (float*)(smem + OFF_WSQ);
    float* tbuf  = (float*)(smem + OFF_TBUF);
    unsigned short* Xh = (unsigned short*)(smem + OFF_XH);
    int*   qpk  = (int*)(smem + OFF_QPK);
    float* qval = (float*)(smem + OFF_QVAL);
    float* redv = (float*)(smem + OFF_REDV);
    float* maxv = (float*)(smem + OFF_MAXV);
    int*   sidx = (int*)(smem + OFF_SIDX);
    float* sred = (float*)(smem + OFF_SRED);
    int*   ctl  = (int*)(smem + OFF_CTL);     // [0]=qn, [1]=sflg

    const int tid  = threadIdx.x;
    const int lane = tid & 31;
    const int warp = tid >> 5;       // 8 warps
    const int g    = lane >> 2;
    const int t    = lane & 3;
    const int wN   = warp & 3;       // 4 N-groups of 32 codes (128/piece)
    const int wM   = warp >> 2;      // 2 M-groups of 32 positions
    const int mi   = lane >> 3;
    const int mr   = lane & 7;

    const int n0  = blockIdx.x * TP;
    const int b   = n0 >> 10;
    const int hw0 = n0 & 1023;
    const float* xin = inp + (((size_t)b * D) << 10) + hw0;

    #pragma unroll
    for (int j = 0; j < 4; ++j)
        wsq_s[tid + j * NTHREADS] = g_wsq[tid + j * NTHREADS];
    if (tid == 0) ctl[0] = 0;
    if (tid < TP) maxv[tid] = -1e30f;

    int parr[4];
    #pragma unroll
    for (int s = 0; s < 4; ++s)
        parr[s] = wM * 32 + (s >> 1) * 16 + (s & 1) * 8 + g;

    uint32_t aXh[2], rB[2];
    #pragma unroll
    for (int mt = 0; mt < 2; ++mt)
        aXh[mt] = sb + OFF_XH +
            (uint32_t)((wM * 32 + mt * 16 + (mi & 1) * 8 + mr) * XROW + (mi >> 1) * 8) * 2;
    #pragma unroll
    for (int q = 0; q < 2; ++q)
        rB[q] = (uint32_t)((wN * 32 + (q * 2 + (mi >> 1)) * 8 + mr) * WROWH + (mi & 1) * 8) * 2;

    // prefetch W piece 0 (codes 0..127, dims 0..63): 4 uint4/thread (MLP=4)
    uint4 fh[4];
    #pragma unroll
    for (int j = 0; j < 4; ++j) {
        int idx = tid + j * NTHREADS;        // 0..1023
        int code = idx >> 3, seg = idx & 7;
        fh[j] = *(const uint4*)(g_whi + (size_t)code * D + seg * 8);
    }

    // ---- X transpose + fp16 hi: 8 slices of 32 dims x 64 pos ----
    for (int dc = 0; dc < 8; ++dc) {
        {
            int d  = tid >> 3;               // 0..31
            int p0 = (tid & 7) << 3;         // 8 positions
            const float* src = xin + (((size_t)(dc * 32 + d)) << 10) + p0;
            float4 v0 = *(const float4*)(src);
            float4 v1 = *(const float4*)(src + 4);
            float* dst = tbuf + d * 68 + p0;
            dst[0]=v0.x; dst[1]=v0.y; dst[2]=v0.z; dst[3]=v0.w;
            dst[4]=v1.x; dst[5]=v1.y; dst[6]=v1.z; dst[7]=v1.w;
        }
        __syncthreads();
        {
            int p  = tid & 63;
            int dq = tid >> 6;               // 0..3 -> dims dq*8..dq*8+7
            uint32_t ph[4];
            #pragma unroll
            for (int i = 0; i < 4; ++i) {
                __half h0 = __float2half_rn(tbuf[(dq * 8 + 2 * i    ) * 68 + p]);
                __half h1 = __float2half_rn(tbuf[(dq * 8 + 2 * i + 1) * 68 + p]);
                ph[i] = (uint32_t)__half_as_ushort(h0) | ((uint32_t)__half_as_ushort(h1) << 16);
            }
            *(uint4*)(Xh + p * XROW + dc * 32 + dq * 8) = make_uint4(ph[0], ph[1], ph[2], ph[3]);
        }
        __syncthreads();
    }

    float acc[2][4][4];
    #pragma unroll
    for (int mt = 0; mt < 2; ++mt)
        #pragma unroll
        for (int nt = 0; nt < 4; ++nt)
            #pragma unroll
            for (int j = 0; j < 4; ++j) acc[mt][nt][j] = 0.f;

    // ---- main loop: 32 pieces = 8 nc (128 codes) x 4 kc (64 dims) ----
    for (int piece = 0; piece < 32; ++piece) {
        const int nc   = piece >> 2;
        const int kc   = piece & 3;
        const int bsel = piece & 1;
        unsigned short* WhB = (unsigned short*)(smem + (bsel ? OFF_WH1 : OFF_WH0));

        #pragma unroll
        for (int j = 0; j < 4; ++j) {
            int idx = tid + j * NTHREADS;
            int code = idx >> 3, seg = idx & 7;
            *(uint4*)(WhB + code * WROWH + seg * 8) = fh[j];
        }
        if (piece + 1 < 32) {
            int nn = (piece + 1) >> 2, nk = (piece + 1) & 3;
            #pragma unroll
            for (int j = 0; j < 4; ++j) {
                int idx = tid + j * NTHREADS;
                int code = idx >> 3, seg = idx & 7;
                fh[j] = *(const uint4*)(g_whi + (size_t)(nn * 128 + code) * D + nk * 64 + seg * 8);
            }
        }
        __syncthreads();   // buffer[bsel] ready; compute on it (piece-2) done

        const uint32_t wbh = sb + (bsel ? OFF_WH1 : OFF_WH0);
        const uint32_t ao0 = (uint32_t)kc * 128;
        #pragma unroll
        for (int ks = 0; ks < 4; ++ks) {
            uint32_t ah0[4], ah1[4], bh[8];
            uint32_t ao = ao0 + ks * 32;
            ldsm4(ah0, aXh[0] + ao);
            ldsm4(ah1, aXh[1] + ao);
            ldsm4(bh + 0, wbh + rB[0] + ks * 32);
            ldsm4(bh + 4, wbh + rB[1] + ks * 32);
            #pragma unroll
            for (int nt = 0; nt < 4; ++nt) {
                mma16816(acc[0][nt], ah0, &bh[nt * 2]);
                mma16816(acc[1][nt], ah1, &bh[nt * 2]);
            }
        }

        if (kc == 3) {
            // finalize chunk scores: s = acc - 0.5||w||^2; chunk max per slot
            float cmax[4] = {-1e30f, -1e30f, -1e30f, -1e30f};
            #pragma unroll
            for (int mt = 0; mt < 2; ++mt)
                #pragma unroll
                for (int nt = 0; nt < 4; ++nt)
                    #pragma unroll
                    for (int j = 0; j < 4; ++j) {
                        int nl = wN * 32 + nt * 8 + 2 * t + (j & 1);
                        float s = acc[mt][nt][j] - wsq_s[nc * 128 + nl];
                        acc[mt][nt][j] = s;
                        int slot = mt * 2 + (j >> 1);
                        cmax[slot] = fmaxf(cmax[slot], s);
                    }
            #pragma unroll
            for (int o = 1; o <= 2; o <<= 1)
                #pragma unroll
                for (int s = 0; s < 4; ++s)
                    cmax[s] = fmaxf(cmax[s], __shfl_xor_sync(0xffffffffu, cmax[s], o));
            if (t == 0) {
                #pragma unroll
                for (int s = 0; s < 4; ++s)
                    redv[parr[s] * 4 + wN] = cmax[s];
            }
            __syncthreads();
            if (tid < TP)
                maxv[tid] = fmaxf(maxv[tid],
                    fmaxf(fmaxf(redv[tid * 4], redv[tid * 4 + 1]),
                          fmaxf(redv[tid * 4 + 2], redv[tid * 4 + 3])));
            __syncthreads();
            // push candidates >= running max - eps (superset of final set)
            #pragma unroll
            for (int mt = 0; mt < 2; ++mt)
                #pragma unroll
                for (int nt = 0; nt < 4; ++nt)
                    #pragma unroll
                    for (int j = 0; j < 4; ++j) {
                        int slot = mt * 2 + (j >> 1);
                        float s = acc[mt][nt][j];
                        if (s >= maxv[parr[slot]] - EPSILON) {
                            int k = nc * 128 + wN * 32 + nt * 8 + 2 * t + (j & 1);
                            int idx = atomicAdd(&ctl[0], 1);
                            if (idx < QCAP) qpk[idx] = (parr[slot] << 16) | k;
                        }
                        acc[mt][nt][j] = 0.f;
                    }
        }
    }
    __syncthreads();
    const int nq = (ctl[0] < QCAP) ? ctl[0] : QCAP;

    // ---- warp-cooperative exact rescue: fp32 x from global (L2-hot), w fp32 ----
    for (int ci = warp; ci < nq; ci += 8) {
        int pk = qpk[ci];
        int cp = pk >> 16, ck = pk & 1023;
        const float* wr = wgt + (size_t)ck * D;
        const float* xr = xin + cp;
        float a = 0.f;
        #pragma unroll
        for (int m = 0; m < 8; ++m) {
            int d = lane + 32 * m;
            a = fmaf(__ldg(xr + (((size_t)d) << 10)), __ldg(wr + d), a);
        }
        #pragma unroll
        for (int o = 16; o > 0; o >>= 1) a += __shfl_xor_sync(0xffffffffu, a, o);
        if (lane == 0) qval[ci] = a - wsq_s[ck];
    }
    __syncthreads();

    // ---- per-position exact argmax over candidates (order-independent) ----
    if (tid < TP) {
        float bv = -1e30f;
        int   bk = 0;
        for (int i = 0; i < nq; ++i) {
            int pk = qpk[i];
            if ((pk >> 16) == tid) {
                float v = qval[i];
                int   k = pk & 1023;
                if (v > bv || (v == bv && k < bk)) { bv = v; bk = k; }
            }
        }
        sidx[tid] = bk;
    }
    __syncthreads();

    // ---- output: gather + NCHW write + loss partial ----
    {
        int p  = tid & 63;
        int ds = tid >> 6;                    // 0..3
        int myidx = sidx[p];
        const float4* wrow = (const float4*)(wgt + (size_t)myidx * D);
        float* op = out + (((size_t)b * D) << 10) + hw0 + p;
        const float* xp = xin + p;
        float lsum = 0.f;
        #pragma unroll 4
        for (int i = 0; i < 16; ++i) {
            int gq = ds + (i << 2);
            float4 qv = __ldg(wrow + gq);
            float x0 = xp[((size_t)(4 * gq + 0)) << 10];
            float x1 = xp[((size_t)(4 * gq + 1)) << 10];
            float x2 = xp[((size_t)(4 * gq + 2)) << 10];
            float x3 = xp[((size_t)(4 * gq + 3)) << 10];
            float d0 = qv.x - x0, d1 = qv.y - x1, d2 = qv.z - x2, d3 = qv.w - x3;
            lsum = fmaf(d0, d0, lsum); lsum = fmaf(d1, d1, lsum);
            lsum = fmaf(d2, d2, lsum); lsum = fmaf(d3, d3, lsum);
            op[((size_t)(4 * gq + 0)) << 10] = qv.x;
            op[((size_t)(4 * gq + 1)) << 10] = qv.y;
            op[((size_t)(4 * gq + 2)) << 10] = qv.z;
            op[((size_t)(4 * gq + 3)) << 10] = qv.w;
        }
        sred[tid] = lsum;
    }
    __syncthreads();
    #pragma unroll
    for (int s = NTHREADS / 2; s > 0; s >>= 1) {
        if (tid < s) sred[tid] += sred[tid + s];
        __syncthreads();
    }
    if (tid == 0) g_partial[blockIdx.x] = sred[0];

    // ---- last-block loss finalize (deterministic; counter self-resets) ----
    if (tid == 0) {
        __threadfence();
        int c = atomicAdd(&g_count, 1);
        ctl[1] = (c == NBLOCKS - 1) ? 1 : 0;
    }
    __syncthreads();
    if (ctl[1]) {
        __threadfence();
        sred[tid] = g_partial[tid] + g_partial[tid + 256];   // NBLOCKS == 512
        __syncthreads();
        #pragma unroll
        for (int s = NTHREADS / 2; s > 0; s >>= 1) {
            if (tid < s) sred[tid] += sred[tid + s];
            __syncthreads();
        }
        if (tid == 0) {
            out[loss_index] = 1.25f * sred[0] / (float)OUT_ELEMS;
            g_count = 0;
        }
    }
}

extern "C" void kernel_launch(void* const* d_in, const int* in_sizes, int n_in,
                              void* d_out, int out_size)
{
    (void)in_sizes; (void)n_in;
    const float* inp = (const float*)d_in[0];   // [32,256,32,32] fp32 NCHW
    const float* wgt = (const float*)d_in[1];   // [1024,256] fp32
    float* out = (float*)d_out;

    (void)cudaFuncSetAttribute(vq_main, cudaFuncAttributeMaxDynamicSharedMemorySize,
                               SMEM_A);

    vq_prep<<<K / 8, 256>>>(wgt);
    vq_main<<<NBLOCKS, NTHREADS, SMEM_A>>>(inp, wgt, out, out_size - 1);
}